// round 6
// baseline (speedup 1.0000x reference)
#include <cuda_runtime.h>

// Problem constants (fixed by the reference setup)
#define NBATCH 32
#define NATOM 256
#define PAIRS_PB 15360
#define NN (NBATCH * PAIRS_PB)      // 491520 total pairs
#define TOTNATOM (NBATCH * NATOM)   // 8192
#define NWAVE 8
#define NSYM 10                     // symmetric channels: 1, x,y,z, xx,xy,xz,yy,yz,zz
#define NORBIT 128
#define CAP 96                      // bin capacity (mean 60, sigma 7.7)
#define SLAB 80                     // floats per atom in g_S: 10 channels x 8 waves
#define ATG2 4                      // atoms per block in hyper_kernel

// Per-atom pair bins: record = {ux|sp(2 low bits), uy, uz, d} = 1 float4 (16 B)
__device__ float4 g_rec[(size_t)TOTNATOM * CAP];   // 12.6 MB (L2-resident)
__device__ int    g_cnt[TOTNATOM];                 // zero-init; moments_kernel resets
// Dual role: overflow red-atomic accumulator (pair) AND final S storage
// (moments overwrites, hyper reads + re-zeroes). Layout [atom][c(10)][w(8)].
__device__ float  g_S[TOTNATOM * SLAB];            // 2.6 MB

__device__ __forceinline__ void red_add_v4(float* ptr, float a, float b, float c, float d) {
    asm volatile("red.global.add.v4.f32 [%0], {%1, %2, %3, %4};"
                 :: "l"(ptr), "f"(a), "f"(b), "f"(c), "f"(d) : "memory");
}
__device__ __forceinline__ float ex2_approx(float x) {
    float r;
    asm("ex2.approx.f32 %0, %1;" : "=f"(r) : "f"(x));
    return r;
}

// ---------------------------------------------------------------------------
// Kernel 1: per-pair geometry + binning (1 int atomic + 1 STG.128 per pair)
// ---------------------------------------------------------------------------
__global__ void __launch_bounds__(256) pair_kernel(
    const float* __restrict__ cart,        // (totnatom, 3)
    const int*   __restrict__ species,     // (totnatom,)
    const int*   __restrict__ atom_index,  // (2, NN) flattened
    const float* __restrict__ shifts,      // (NN, 3)
    const float* __restrict__ rs,          // (NTYPE, 8)
    const float* __restrict__ inta,        // (NTYPE, 8)
    const float* __restrict__ params)      // (NTYPE, 8)
{
    int p = blockIdx.x * blockDim.x + threadIdx.x;
    if (p >= NN) return;

    int b = p / PAIRS_PB;
    int i = atom_index[p]      + b * NATOM;   // center (segment target)
    int j = atom_index[NN + p] + b * NATOM;   // neighbor

    // Claim slot early: the ~300-cycle atomic round-trip overlaps the math below.
    int slot = atomicAdd(&g_cnt[i], 1);

    float dx = __ldg(&cart[3 * i + 0]) - __ldg(&cart[3 * j + 0]) + __ldg(&shifts[3 * p + 0]);
    float dy = __ldg(&cart[3 * i + 1]) - __ldg(&cart[3 * j + 1]) + __ldg(&shifts[3 * p + 1]);
    float dz = __ldg(&cart[3 * i + 2]) - __ldg(&cart[3 * j + 2]) + __ldg(&shifts[3 * p + 2]);

    float d2  = dx * dx + dy * dy + dz * dz;
    float inv = rsqrtf(d2);
    float d   = d2 * inv;                 // |r|
    float ux = dx * inv, uy = dy * inv, uz = dz * inv;

    int sp = __ldg(&species[j]);

    if (slot < CAP) {
        // pack species into 2 low mantissa bits of ux (<=3 ulp perturbation)
        unsigned uxb = (__float_as_uint(ux) & ~3u) | (unsigned)sp;
        g_rec[(size_t)i * CAP + slot] = make_float4(__uint_as_float(uxb), uy, uz, d);
    } else {
        // Overflow fallback (expected never taken): exact red-atomic scatter
        float rc[NWAVE];
#pragma unroll
        for (int w = 0; w < NWAVE; w++) {
            float t = d - __ldg(&rs[sp * NWAVE + w]);
            rc[w] = __expf(__ldg(&inta[sp * NWAVE + w]) * t * t) * __ldg(&params[sp * NWAVE + w]);
        }
        float ang[NSYM] = {1.f, ux, uy, uz,
                           ux * ux, ux * uy, ux * uz, uy * uy, uy * uz, uz * uz};
        float* Sa = g_S + (size_t)i * SLAB;
#pragma unroll
        for (int c = 0; c < NSYM; c++) {
            float a = ang[c];
            red_add_v4(Sa + c * NWAVE,     a * rc[0], a * rc[1], a * rc[2], a * rc[3]);
            red_add_v4(Sa + c * NWAVE + 4, a * rc[4], a * rc[5], a * rc[6], a * rc[7]);
        }
    }
}

// ---------------------------------------------------------------------------
// Kernel 2: moments — ONE WARP PER ATOM. Lane = (quarter q, wave w).
// Each lane accumulates sym moments over its bin quarter; quarters combined
// with shfl.xor; sqrt(channel weight) folded; S stored to g_S.
// Resets g_cnt. No block barrier in the hot path.
// ---------------------------------------------------------------------------
__global__ void __launch_bounds__(256) moments_kernel(
    const float* __restrict__ rs,      // (NTYPE, 8)
    const float* __restrict__ inta,    // (NTYPE, 8)
    const float* __restrict__ params)  // (NTYPE, 8)
{
    const int tid  = threadIdx.x;
    const int lane = tid & 31;
    const int q    = lane >> 3;        // bin quarter 0..3
    const int w    = lane & 7;         // wave index 0..7
    const int a    = blockIdx.x * 8 + (tid >> 5);

    __shared__ float Trs[32], TA[32], TP[32];
    if (tid < 32) {
        Trs[tid] = __ldg(&rs[tid]);
        TA[tid]  = __ldg(&inta[tid]) * 1.4426950408889634f;   // fold log2(e)
        TP[tid]  = __ldg(&params[tid]);
    }
    __syncthreads();

    const int n  = g_cnt[a];
    const int nc = min(n, CAP);
    if (lane == 0) g_cnt[a] = 0;       // reset for next replay

    float acc[NSYM];
    if (n > CAP && q == 0) {           // overflow init (expected never; q==0 only)
        const float* gs = g_S + (size_t)a * SLAB;
#pragma unroll
        for (int c = 0; c < NSYM; c++) acc[c] = gs[c * NWAVE + w];
    } else {
#pragma unroll
        for (int c = 0; c < NSYM; c++) acc[c] = 0.f;
    }

    const float4* rec = g_rec + (size_t)a * CAP;
#pragma unroll 4
    for (int p = q; p < nc; p += 4) {
        float4 r = __ldg(&rec[p]);                 // 4 distinct addrs/warp, 8-lane bcast
        unsigned uxb = __float_as_uint(r.x);
        int sp8 = (int)(uxb & 3u) * NWAVE + w;
        float ux = __uint_as_float(uxb & ~3u);
        float t  = r.w - Trs[sp8];
        float rc = ex2_approx(TA[sp8] * t * t) * TP[sp8];

        acc[0] += rc;
        float tx = rc * ux, ty = rc * r.y, tz = rc * r.z;
        acc[1] += tx;       acc[2] += ty;       acc[3] += tz;
        acc[4] += tx * ux;  acc[5] += tx * r.y; acc[6] += tx * r.z;
        acc[7] += ty * r.y; acc[8] += ty * r.z; acc[9] += tz * r.z;
    }

    // Combine the 4 quarters: butterfly across lane bits 3,4 (same w lanes)
#pragma unroll
    for (int c = 0; c < NSYM; c++) {
        acc[c] += __shfl_xor_sync(0xffffffffu, acc[c], 8);
        acc[c] += __shfl_xor_sync(0xffffffffu, acc[c], 16);
    }

    // Store weighted S (sqrt of channel weight {1,1,1,1,1,2,2,1,2,1} folded)
    if (q == 0) {
        const float SQ2 = 1.41421356237309515f;
        const float scl[NSYM] = {1.f, 1.f, 1.f, 1.f, 1.f, SQ2, SQ2, 1.f, SQ2, 1.f};
        float* Sa = g_S + (size_t)a * SLAB;
#pragma unroll
        for (int c = 0; c < NSYM; c++)
            Sa[c * NWAVE + w] = acc[c] * scl[c];
    }
}

// ---------------------------------------------------------------------------
// Kernel 3: hyper contraction. 4 atoms/block, 128 threads, grid 2048.
// Loads S slabs to smem (and re-zeroes g_S for the overflow invariant),
// thread owns orbit column m, loops 4 atoms.
// ---------------------------------------------------------------------------
__global__ void __launch_bounds__(128) hyper_kernel(
    const float* __restrict__ hyper,   // (3, 8, 128)
    float* __restrict__ out)           // (totnatom, 128)
{
    const int tid = threadIdx.x;
    const int a0  = blockIdx.x * ATG2;

    __shared__ float Ssm[ATG2 * SLAB];   // 320 floats

    float* gs = g_S + (size_t)a0 * SLAB;
#pragma unroll
    for (int idx = tid; idx < ATG2 * SLAB; idx += 128) {
        Ssm[idx] = gs[idx];
        gs[idx]  = 0.f;                  // restore overflow-accumulator invariant
    }

    const int m = tid;
    float h[3][NWAVE];
#pragma unroll
    for (int k = 0; k < 3; k++)
#pragma unroll
        for (int v = 0; v < NWAVE; v++)
            h[k][v] = __ldg(&hyper[(k * NWAVE + v) * NORBIT + m]);

    __syncthreads();

    const int k_of[NSYM] = {0, 1, 1, 1, 2, 2, 2, 2, 2, 2};

#pragma unroll 1
    for (int la = 0; la < ATG2; la++) {
        const float* S = Ssm + la * SLAB;
        float dens = 0.f;
#pragma unroll
        for (int c = 0; c < NSYM; c++) {
            const int k = k_of[c];
            float4 s0 = *(const float4*)(S + c * NWAVE);
            float4 s1 = *(const float4*)(S + c * NWAVE + 4);
            float t = s0.x * h[k][0] + s0.y * h[k][1] + s0.z * h[k][2] + s0.w * h[k][3]
                    + s1.x * h[k][4] + s1.y * h[k][5] + s1.z * h[k][6] + s1.w * h[k][7];
            dens += t * t;
        }
        out[(a0 + la) * NORBIT + m] = dens;
    }
}

// ---------------------------------------------------------------------------
// Launch (3 kernels; counters + overflow slab self-reset)
// ---------------------------------------------------------------------------
extern "C" void kernel_launch(void* const* d_in, const int* in_sizes, int n_in,
                              void* d_out, int out_size) {
    const float* cart       = (const float*)d_in[0];
    // d_in[1] = numatoms (unused by the reference math)
    const int*   species    = (const int*)  d_in[2];
    const int*   atom_index = (const int*)  d_in[3];
    const float* shifts     = (const float*)d_in[4];
    const float* rs         = (const float*)d_in[5];
    const float* inta       = (const float*)d_in[6];
    const float* params     = (const float*)d_in[7];
    const float* hyper      = (const float*)d_in[8];
    float* out = (float*)d_out;

    pair_kernel<<<(NN + 255) / 256, 256>>>(cart, species, atom_index, shifts,
                                           rs, inta, params);
    moments_kernel<<<TOTNATOM / 8, 256>>>(rs, inta, params);
    hyper_kernel<<<TOTNATOM / ATG2, 128>>>(hyper, out);
}

// round 7
// speedup vs baseline: 1.2642x; 1.2642x over previous
#include <cuda_runtime.h>

// Problem constants (fixed by the reference setup)
#define NBATCH 32
#define NATOM 256
#define PAIRS_PB 15360
#define NN (NBATCH * PAIRS_PB)      // 491520 total pairs
#define TOTNATOM (NBATCH * NATOM)   // 8192
#define NWAVE 8
#define NSYM 10                     // symmetric channels: 1, x,y,z, xx,xy,xz,yy,yz,zz
#define NORBIT 128
#define CAP 96                      // bin capacity (mean 60, sigma 7.7)
#define APB 8                       // atoms per block (gather)
#define HSTRIDE 80                  // floats per (atom,half) slab: 10*8
#define PBATCH 4                    // pairs per thread in pair_kernel

// Per-atom pair bins: record = {ux|sp(2 low bits), uy, uz, d} = 1 float4 (16 B)
__device__ float4 g_rec[(size_t)TOTNATOM * CAP];       // 12.6 MB (L2-resident)
__device__ int    g_cnt[TOTNATOM];                     // zero-init (.bss); gather resets
// Overflow fallback accumulator [atom][c(10)][w(8)]; gather re-zeroes on use
__device__ float4 g_S[TOTNATOM * (NSYM * NWAVE / 4)];  // 2.6 MB

__device__ __forceinline__ void red_add_v4(float4* ptr, float a, float b, float c, float d) {
    asm volatile("red.global.add.v4.f32 [%0], {%1, %2, %3, %4};"
                 :: "l"(ptr), "f"(a), "f"(b), "f"(c), "f"(d) : "memory");
}
__device__ __forceinline__ float ex2_approx(float x) {
    float r;
    asm("ex2.approx.f32 %0, %1;" : "=f"(r) : "f"(x));
    return r;
}

// ---------------------------------------------------------------------------
// Kernel 1: per-pair geometry + binning, 4 pairs/thread software-pipelined:
// all index loads -> all 4 atomics -> all cart/shift loads -> compute+store.
// Four independent atomic->store chains per thread hide the L2 round-trips.
// ---------------------------------------------------------------------------
__global__ void __launch_bounds__(256) pair_kernel(
    const float* __restrict__ cart,        // (totnatom, 3)
    const int*   __restrict__ species,     // (totnatom,)
    const int*   __restrict__ atom_index,  // (2, NN) flattened
    const float* __restrict__ shifts,      // (NN, 3)
    const float* __restrict__ rs,          // (NTYPE, 8)
    const float* __restrict__ inta,        // (NTYPE, 8)
    const float* __restrict__ params)      // (NTYPE, 8)
{
    const int QT = NN / PBATCH;
    const int t  = blockIdx.x * blockDim.x + threadIdx.x;
    if (t >= QT) return;

    int pp[PBATCH], ii[PBATCH], jj[PBATCH], slot[PBATCH];

    // Phase A: index loads (coalesced in all 4 streams)
#pragma unroll
    for (int k = 0; k < PBATCH; k++) {
        int p = t + k * QT;
        int b = p / PAIRS_PB;
        pp[k] = p;
        ii[k] = __ldg(&atom_index[p])      + b * NATOM;
        jj[k] = __ldg(&atom_index[NN + p]) + b * NATOM;
    }

    // Phase B: fire all slot atomics (4 L2 round-trips overlap)
#pragma unroll
    for (int k = 0; k < PBATCH; k++)
        slot[k] = atomicAdd(&g_cnt[ii[k]], 1);

    // Phase C: geometry loads for all 4 pairs
    float dx[PBATCH], dy[PBATCH], dz[PBATCH];
#pragma unroll
    for (int k = 0; k < PBATCH; k++) {
        dx[k] = __ldg(&cart[3 * ii[k] + 0]) - __ldg(&cart[3 * jj[k] + 0]) + __ldg(&shifts[3 * pp[k] + 0]);
        dy[k] = __ldg(&cart[3 * ii[k] + 1]) - __ldg(&cart[3 * jj[k] + 1]) + __ldg(&shifts[3 * pp[k] + 1]);
        dz[k] = __ldg(&cart[3 * ii[k] + 2]) - __ldg(&cart[3 * jj[k] + 2]) + __ldg(&shifts[3 * pp[k] + 2]);
    }

    // Phase D: compute + store
#pragma unroll
    for (int k = 0; k < PBATCH; k++) {
        float d2  = dx[k] * dx[k] + dy[k] * dy[k] + dz[k] * dz[k];
        float inv = rsqrtf(d2);
        float d   = d2 * inv;                 // |r|
        float ux = dx[k] * inv, uy = dy[k] * inv, uz = dz[k] * inv;
        int sp = __ldg(&species[jj[k]]);

        if (slot[k] < CAP) {
            // pack species into 2 low mantissa bits of ux (<=3 ulp perturbation)
            unsigned uxb = (__float_as_uint(ux) & ~3u) | (unsigned)sp;
            g_rec[(size_t)ii[k] * CAP + slot[k]] = make_float4(__uint_as_float(uxb), uy, uz, d);
        } else {
            // Overflow fallback (expected never taken): exact red-atomic scatter
            float rc[NWAVE];
#pragma unroll
            for (int w = 0; w < NWAVE; w++) {
                float tt = d - __ldg(&rs[sp * NWAVE + w]);
                rc[w] = __expf(__ldg(&inta[sp * NWAVE + w]) * tt * tt) * __ldg(&params[sp * NWAVE + w]);
            }
            float ang[NSYM] = {1.f, ux, uy, uz,
                               ux * ux, ux * uy, ux * uz, uy * uy, uy * uz, uz * uz};
            float4* Sa = g_S + (size_t)ii[k] * (NSYM * NWAVE / 4);
#pragma unroll
            for (int c = 0; c < NSYM; c++) {
                float a = ang[c];
                red_add_v4(&Sa[2 * c + 0], a * rc[0], a * rc[1], a * rc[2], a * rc[3]);
                red_add_v4(&Sa[2 * c + 1], a * rc[4], a * rc[5], a * rc[6], a * rc[7]);
            }
        }
    }
}

// ---------------------------------------------------------------------------
// Kernel 2: gather + hyper contraction (R3-proven shape).
// 8 atoms/block, 128 threads, grid 1024.
// Phase 1: 16 threads/atom = (half 0/1) x (w 0..7); interleaved bin halves.
// Phase 2: combine halves in smem, folding sqrt(channel weight).
// Phase 3: thread owns orbit column m, loops 8 atoms.
// Also resets g_cnt (and g_S if overflow) for the next graph replay.
// ---------------------------------------------------------------------------
__global__ void __launch_bounds__(128) gather_kernel(
    const float* __restrict__ rs,      // (NTYPE, 8)
    const float* __restrict__ inta,    // (NTYPE, 8)
    const float* __restrict__ params,  // (NTYPE, 8)
    const float* __restrict__ hyper,   // (3, 8, 128)
    float* __restrict__ out)           // (totnatom, 128)
{
    const int tid  = threadIdx.x;
    const int la   = tid >> 4;         // local atom 0..7
    const int half = (tid >> 3) & 1;   // bin half 0/1
    const int w    = tid & 7;          // wave index 0..7
    const int a    = blockIdx.x * APB + la;

    __shared__ float Trs[32], TA[32], TP[32];            // species tables
    __shared__ float Ssm[APB * 2 * HSTRIDE];             // 5 KB

    if (tid < 32) {
        Trs[tid] = __ldg(&rs[tid]);
        TA[tid]  = __ldg(&inta[tid]) * 1.4426950408889634f;   // fold log2(e)
        TP[tid]  = __ldg(&params[tid]);
    }
    __syncthreads();

    // ---- Phase 1: per-(atom, half, w) symmetric moment accumulation ----
    const int n  = g_cnt[a];
    const int nc = min(n, CAP);
    if ((tid & 15) == 0) g_cnt[a] = 0;     // reset for next replay

    float acc[NSYM];
    if (n > CAP && half == 0) {            // overflow init + re-zero (expected never)
        float* gs = (float*)(g_S + (size_t)a * (NSYM * NWAVE / 4));
#pragma unroll
        for (int c = 0; c < NSYM; c++) {
            acc[c] = gs[c * NWAVE + w];
            gs[c * NWAVE + w] = 0.f;
        }
    } else {
#pragma unroll
        for (int c = 0; c < NSYM; c++) acc[c] = 0.f;
    }

    const float4* rec = g_rec + (size_t)a * CAP;
#pragma unroll 4
    for (int p = half; p < nc; p += 2) {
        float4 r = __ldg(&rec[p]);                 // broadcast across the 8 w-threads
        unsigned uxb = __float_as_uint(r.x);
        int sp8 = (int)(uxb & 3u) * NWAVE + w;
        float ux = __uint_as_float(uxb & ~3u);
        float t  = r.w - Trs[sp8];
        float rc = ex2_approx(TA[sp8] * t * t) * TP[sp8];

        acc[0] += rc;
        float tx = rc * ux, ty = rc * r.y, tz = rc * r.z;
        acc[1] += tx;       acc[2] += ty;       acc[3] += tz;
        acc[4] += tx * ux;  acc[5] += tx * r.y; acc[6] += tx * r.z;
        acc[7] += ty * r.y; acc[8] += ty * r.z; acc[9] += tz * r.z;
    }

    // ---- Phase 2: stash halves, then combine with sqrt(weight) fold ----
#pragma unroll
    for (int c = 0; c < NSYM; c++)
        Ssm[(la * 2 + half) * HSTRIDE + c * NWAVE + w] = acc[c];
    __syncthreads();

    {
        // channel weights {1,1,1,1,1,2,2,1,2,1} -> sqrt folded into S
        const float SQ2 = 1.41421356237309515f;
        const float scl[NSYM] = {1.f, 1.f, 1.f, 1.f, 1.f, SQ2, SQ2, 1.f, SQ2, 1.f};
#pragma unroll
        for (int idx = tid; idx < APB * HSTRIDE; idx += 128) {
            int at  = idx / HSTRIDE;
            int cw  = idx - at * HSTRIDE;
            float v = Ssm[(at * 2) * HSTRIDE + cw] + Ssm[(at * 2 + 1) * HSTRIDE + cw];
            Ssm[(at * 2) * HSTRIDE + cw] = v * scl[cw >> 3];
        }
    }
    __syncthreads();

    // ---- Phase 3: hyper contraction; thread = orbit column m ----
    const int m = tid;
    float h[3][NWAVE];
#pragma unroll
    for (int k = 0; k < 3; k++)
#pragma unroll
        for (int v = 0; v < NWAVE; v++)
            h[k][v] = __ldg(&hyper[(k * NWAVE + v) * NORBIT + m]);

    const int k_of[NSYM] = {0, 1, 1, 1, 2, 2, 2, 2, 2, 2};

#pragma unroll 1
    for (int la2 = 0; la2 < APB; la2++) {
        const float* S = Ssm + (la2 * 2) * HSTRIDE;
        float dens = 0.f;
#pragma unroll
        for (int c = 0; c < NSYM; c++) {
            const int k = k_of[c];
            float4 s0 = *(const float4*)(S + c * NWAVE);
            float4 s1 = *(const float4*)(S + c * NWAVE + 4);
            float t = s0.x * h[k][0] + s0.y * h[k][1] + s0.z * h[k][2] + s0.w * h[k][3]
                    + s1.x * h[k][4] + s1.y * h[k][5] + s1.z * h[k][6] + s1.w * h[k][7];
            dens += t * t;
        }
        out[(blockIdx.x * APB + la2) * NORBIT + m] = dens;
    }
}

// ---------------------------------------------------------------------------
// Launch (2 kernels; counters self-reset inside gather)
// ---------------------------------------------------------------------------
extern "C" void kernel_launch(void* const* d_in, const int* in_sizes, int n_in,
                              void* d_out, int out_size) {
    const float* cart       = (const float*)d_in[0];
    // d_in[1] = numatoms (unused by the reference math)
    const int*   species    = (const int*)  d_in[2];
    const int*   atom_index = (const int*)  d_in[3];
    const float* shifts     = (const float*)d_in[4];
    const float* rs         = (const float*)d_in[5];
    const float* inta       = (const float*)d_in[6];
    const float* params     = (const float*)d_in[7];
    const float* hyper      = (const float*)d_in[8];
    float* out = (float*)d_out;

    pair_kernel<<<(NN / PBATCH + 255) / 256, 256>>>(cart, species, atom_index, shifts,
                                                    rs, inta, params);
    gather_kernel<<<TOTNATOM / APB, 128>>>(rs, inta, params, hyper, out);
}